// round 5
// baseline (speedup 1.0000x reference)
#include <cuda_runtime.h>
#include <cuda_bf16.h>
#include <mma.h>

using namespace nvcuda;
typedef __nv_bfloat16 bf16;

#define BATCH 4
#define SEQ   4096
#define CH    1024
#define NHEAD 16
#define DH    64
#define MROWS (BATCH*SEQ)     /* 16384 */
#define KDIM  CH              /* 1024  */
#define NQKV  (3*CH)          /* 3072  */
#define NSPLIT 16
#define BHCNT (BATCH*NHEAD)   /* 64    */

// ------------------------- scratch (device globals; no allocs) -------------------------
__device__ bf16  g_x_hi[(size_t)MROWS*KDIM];
__device__ bf16  g_x_lo[(size_t)MROWS*KDIM];
__device__ bf16  g_wqkv_hi[(size_t)NQKV*KDIM];
__device__ bf16  g_wqkv_lo[(size_t)NQKV*KDIM];
__device__ bf16  g_wout_hi[(size_t)CH*KDIM];
__device__ bf16  g_wout_lo[(size_t)CH*KDIM];
__device__ float g_qkv[(size_t)MROWS*NQKV];                  // feat applied to q,k cols
__device__ float g_kv_part[(size_t)NSPLIT*BHCNT*DH*DH];
__device__ float g_ksum_part[(size_t)NSPLIT*BHCNT*DH];
__device__ float g_kv[(size_t)BHCNT*DH*DH];
__device__ float g_denom[(size_t)BHCNT*SEQ];                 // stores 1/(denom+eps)
__device__ bf16  g_attn_hi[(size_t)MROWS*CH];
__device__ bf16  g_attn_lo[(size_t)MROWS*CH];

// ------------------------- helpers -------------------------
__device__ __forceinline__ float featf(float x) {
    const float s = 0.35355339059327373f;       // 64^-0.25
    return (x > 0.0f) ? (x + 1.0f) * s : __expf(x) * s;
}

// ------------------------- split fp32 -> bf16 hi/lo -------------------------
// mode: 0 = x, 1 = w_qkv, 2 = w_out
__global__ void split_kernel(const float* __restrict__ src, int n, int mode) {
    bf16 *hi, *lo;
    if (mode == 0)      { hi = g_x_hi;    lo = g_x_lo; }
    else if (mode == 1) { hi = g_wqkv_hi; lo = g_wqkv_lo; }
    else                { hi = g_wout_hi; lo = g_wout_lo; }
    int i = blockIdx.x * blockDim.x + threadIdx.x;
    int stride = gridDim.x * blockDim.x;
    for (; i < n; i += stride) {
        float v = src[i];
        bf16 h = __float2bfloat16(v);
        float r = v - __bfloat162float(h);
        hi[i] = h;
        lo[i] = __float2bfloat16(r);
    }
}

// ------------------------- bf16x3 GEMM: C[m,n] = sum_k A[m,k]*B[n,k] -------------------------
#define BM 128
#define BN 128
#define BKT 32
#define LDA 40   /* BKT + 8 pad, bf16 elems */
#define GEMM_SMEM (4*2*BM*LDA*sizeof(bf16))   /* 81920 B; epilogue reuse needs 67584 B */

template<int MODE>   // MODE 0: x@wqkv^T (feat epilogue -> g_qkv). MODE 1: attn@wout^T + bias -> Cout.
__global__ void __launch_bounds__(256) gemm_bf16x3(float* __restrict__ CoutExt,
                                                   const float* __restrict__ bias) {
    constexpr int NC = (MODE == 0) ? NQKV : CH;
    const bf16* __restrict__ Ahi = (MODE == 0) ? g_x_hi    : g_attn_hi;
    const bf16* __restrict__ Alo = (MODE == 0) ? g_x_lo    : g_attn_lo;
    const bf16* __restrict__ Bhi = (MODE == 0) ? g_wqkv_hi : g_wout_hi;
    const bf16* __restrict__ Blo = (MODE == 0) ? g_wqkv_lo : g_wout_lo;
    float* __restrict__ Cp = (MODE == 0) ? g_qkv : CoutExt;

    extern __shared__ __align__(16) char smem_raw[];
    bf16* sA_h = (bf16*)smem_raw;
    bf16* sA_l = sA_h + 2*BM*LDA;
    bf16* sB_h = sA_l + 2*BM*LDA;
    bf16* sB_l = sB_h + 2*BM*LDA;

    const int tid = threadIdx.x;
    const int wid = tid >> 5;
    const int wm_ = wid >> 1;    // 0..3 (M dir)
    const int wn_ = wid & 1;     // 0..1 (N dir)
    const int m0 = blockIdx.y * BM;
    const int n0 = blockIdx.x * BN;

    const int r0 = tid >> 2;
    const int c0 = (tid & 3) << 3;
    const int r1 = r0 + 64;
    const int so0 = r0*LDA + c0;
    const int so1 = r1*LDA + c0;
    const size_t ga0 = (size_t)(m0 + r0)*KDIM + c0;
    const size_t ga1 = (size_t)(m0 + r1)*KDIM + c0;
    const size_t gb0 = (size_t)(n0 + r0)*KDIM + c0;
    const size_t gb1 = (size_t)(n0 + r1)*KDIM + c0;

    wmma::fragment<wmma::accumulator,16,16,16,float> acc[2][4];
    #pragma unroll
    for (int i = 0; i < 2; i++)
        #pragma unroll
        for (int j = 0; j < 4; j++) wmma::fill_fragment(acc[i][j], 0.0f);

    // tile 0
    *(uint4*)(sA_h + so0) = *(const uint4*)(Ahi + ga0);
    *(uint4*)(sA_h + so1) = *(const uint4*)(Ahi + ga1);
    *(uint4*)(sA_l + so0) = *(const uint4*)(Alo + ga0);
    *(uint4*)(sA_l + so1) = *(const uint4*)(Alo + ga1);
    *(uint4*)(sB_h + so0) = *(const uint4*)(Bhi + gb0);
    *(uint4*)(sB_h + so1) = *(const uint4*)(Bhi + gb1);
    *(uint4*)(sB_l + so0) = *(const uint4*)(Blo + gb0);
    *(uint4*)(sB_l + so1) = *(const uint4*)(Blo + gb1);
    __syncthreads();

    const int NT = KDIM / BKT;  // 32
    for (int kt = 0; kt < NT; ++kt) {
        uint4 p0,p1,p2,p3,p4,p5,p6,p7;
        if (kt + 1 < NT) {
            const size_t ko = (size_t)(kt + 1) * BKT;
            p0 = *(const uint4*)(Ahi + ga0 + ko);
            p1 = *(const uint4*)(Ahi + ga1 + ko);
            p2 = *(const uint4*)(Alo + ga0 + ko);
            p3 = *(const uint4*)(Alo + ga1 + ko);
            p4 = *(const uint4*)(Bhi + gb0 + ko);
            p5 = *(const uint4*)(Bhi + gb1 + ko);
            p6 = *(const uint4*)(Blo + gb0 + ko);
            p7 = *(const uint4*)(Blo + gb1 + ko);
        }
        const int buf = (kt & 1) * BM * LDA;
        const bf16* pAh = sA_h + buf + wm_*32*LDA;
        const bf16* pAl = sA_l + buf + wm_*32*LDA;
        const bf16* pBh = sB_h + buf + wn_*64*LDA;
        const bf16* pBl = sB_l + buf + wn_*64*LDA;
        #pragma unroll
        for (int ks = 0; ks < BKT; ks += 16) {
            wmma::fragment<wmma::matrix_a,16,16,16,bf16,wmma::row_major> ah[2], al[2];
            wmma::fragment<wmma::matrix_b,16,16,16,bf16,wmma::col_major> bh[4], bl[4];
            #pragma unroll
            for (int i = 0; i < 2; i++) {
                wmma::load_matrix_sync(ah[i], pAh + i*16*LDA + ks, LDA);
                wmma::load_matrix_sync(al[i], pAl + i*16*LDA + ks, LDA);
            }
            #pragma unroll
            for (int j = 0; j < 4; j++) {
                wmma::load_matrix_sync(bh[j], pBh + j*16*LDA + ks, LDA);
                wmma::load_matrix_sync(bl[j], pBl + j*16*LDA + ks, LDA);
            }
            #pragma unroll
            for (int i = 0; i < 2; i++)
                #pragma unroll
                for (int j = 0; j < 4; j++) {
                    wmma::mma_sync(acc[i][j], ah[i], bh[j], acc[i][j]);
                    wmma::mma_sync(acc[i][j], ah[i], bl[j], acc[i][j]);
                    wmma::mma_sync(acc[i][j], al[i], bh[j], acc[i][j]);
                }
        }
        if (kt + 1 < NT) {
            const int nb = ((kt + 1) & 1) * BM * LDA;
            *(uint4*)(sA_h + nb + so0) = p0;
            *(uint4*)(sA_h + nb + so1) = p1;
            *(uint4*)(sA_l + nb + so0) = p2;
            *(uint4*)(sA_l + nb + so1) = p3;
            *(uint4*)(sB_h + nb + so0) = p4;
            *(uint4*)(sB_h + nb + so1) = p5;
            *(uint4*)(sB_l + nb + so0) = p6;
            *(uint4*)(sB_l + nb + so1) = p7;
        }
        __syncthreads();
    }

    // epilogue: stage accumulators in smem, then vectorized global store with fusion
    float* Cs = (float*)smem_raw;   // 128 x 132 floats = 67584 B
    #pragma unroll
    for (int i = 0; i < 2; i++)
        #pragma unroll
        for (int j = 0; j < 4; j++)
            wmma::store_matrix_sync(Cs + (wm_*32 + i*16)*132 + wn_*64 + j*16,
                                    acc[i][j], 132, wmma::mem_row_major);
    __syncthreads();
    for (int i = tid; i < BM*BN/4; i += 256) {
        const int row = i >> 5;
        const int c4  = (i & 31) << 2;
        float4 v = *(const float4*)&Cs[row*132 + c4];
        const int gn = n0 + c4;
        if (MODE == 0) {
            if (gn < 2*CH) {  // q and k columns get elu+1 and scale
                v.x = featf(v.x); v.y = featf(v.y); v.z = featf(v.z); v.w = featf(v.w);
            }
        } else {
            v.x += bias[gn]; v.y += bias[gn+1]; v.z += bias[gn+2]; v.w += bias[gn+3];
        }
        *(float4*)&Cp[(size_t)(m0 + row)*NC + gn] = v;
    }
}

// ------------------------- kv = k^T v partials + ksum partials -------------------------
__global__ void __launch_bounds__(256) kv_partial_kernel() {
    const int s  = blockIdx.x;          // 0..15 (N split)
    const int bh = blockIdx.y;          // 0..63
    const int b = bh >> 4, h = bh & 15;
    const int tid = threadIdx.x;
    const int d  = tid >> 2;            // 0..63
    const int e0 = (tid & 3) << 4;      // 0,16,32,48

    __shared__ __align__(16) float ks_[8][64];
    __shared__ __align__(16) float vs_[8][64];

    float acc[16];
    #pragma unroll
    for (int i = 0; i < 16; i++) acc[i] = 0.0f;
    float ksum = 0.0f;

    const float* kbase = g_qkv + (size_t)(b*SEQ)*NQKV + CH + h*DH;
    const float* vbase = kbase + CH;
    int nbase = s * (SEQ / NSPLIT);     // 256 rows per block
    for (int it = 0; it < 32; ++it, nbase += 8) {
        #pragma unroll
        for (int j = 0; j < 2; ++j) {
            const int idx = tid + j*256;
            const int r = idx >> 6, c = idx & 63;
            ks_[r][c] = kbase[(size_t)(nbase + r)*NQKV + c];
            vs_[r][c] = vbase[(size_t)(nbase + r)*NQKV + c];
        }
        __syncthreads();
        #pragma unroll
        for (int r = 0; r < 8; ++r) {
            const float kd = ks_[r][d];
            ksum += kd;
            #pragma unroll
            for (int j4 = 0; j4 < 4; ++j4) {
                const float4 vv = *(const float4*)&vs_[r][e0 + j4*4];
                acc[j4*4+0] += kd*vv.x; acc[j4*4+1] += kd*vv.y;
                acc[j4*4+2] += kd*vv.z; acc[j4*4+3] += kd*vv.w;
            }
        }
        __syncthreads();
    }
    float* outp = g_kv_part + ((size_t)s*BHCNT + bh)*(DH*DH) + d*DH + e0;
    #pragma unroll
    for (int j4 = 0; j4 < 4; ++j4)
        *(float4*)&outp[j4*4] = make_float4(acc[j4*4], acc[j4*4+1], acc[j4*4+2], acc[j4*4+3]);
    if ((tid & 3) == 0)
        g_ksum_part[((size_t)s*BHCNT + bh)*DH + d] = ksum;
}

__global__ void kv_reduce_kernel() {
    const int i = blockIdx.x * 256 + threadIdx.x;   // 0..262143
    float s = 0.0f;
    #pragma unroll
    for (int p = 0; p < NSPLIT; ++p) s += g_kv_part[(size_t)p*(BHCNT*DH*DH) + i];
    g_kv[i] = s;
}

// ------------------------- ksum reduce + denom^-1 -------------------------
__global__ void __launch_bounds__(256) denom_kernel() {
    const int bh = blockIdx.y;
    const int b = bh >> 4, h = bh & 15;
    const int tid = threadIdx.x;
    __shared__ float ksum_s[64];
    if (tid < 64) {
        float s = 0.0f;
        #pragma unroll
        for (int p = 0; p < NSPLIT; ++p) s += g_ksum_part[((size_t)p*BHCNT + bh)*DH + tid];
        ksum_s[tid] = s;
    }
    __syncthreads();
    const int n = blockIdx.x * 256 + tid;
    const float* qp = g_qkv + (size_t)(b*SEQ + n)*NQKV + h*DH;
    float a = 0.0f;
    #pragma unroll
    for (int d4 = 0; d4 < DH; d4 += 4) {
        const float4 q4 = *(const float4*)&qp[d4];
        a += q4.x*ksum_s[d4] + q4.y*ksum_s[d4+1] + q4.z*ksum_s[d4+2] + q4.w*ksum_s[d4+3];
    }
    g_denom[(size_t)bh*SEQ + n] = 1.0f / (a + 1e-6f);
}

// ------------------------- out = (q @ kv) * denom^-1, split to bf16 hi/lo -------------------------
__global__ void __launch_bounds__(256) attn_kernel() {
    const int bh = blockIdx.y;
    const int chunk = blockIdx.x;                    // 64 chunks x 64 rows
    const int b = bh >> 4, h = bh & 15;
    const int tid = threadIdx.x;
    const int base = chunk * 64;

    __shared__ __align__(16) float kv_s[64*64];
    __shared__ float q_s[64*65];
    __shared__ float inv_s[64];

    for (int i = tid; i < DH*DH; i += 256) kv_s[i] = g_kv[(size_t)bh*(DH*DH) + i];
    for (int i = tid; i < 64*64; i += 256) {
        const int r = i >> 6, d = i & 63;
        q_s[r*65 + d] = g_qkv[(size_t)(b*SEQ + base + r)*NQKV + h*DH + d];
    }
    if (tid < 64) inv_s[tid] = g_denom[(size_t)bh*SEQ + base + tid];
    __syncthreads();

    const int rsub = tid >> 4;          // 0..15
    const int e4   = (tid & 15) << 2;   // 0..60
    #pragma unroll
    for (int p = 0; p < 4; ++p) {
        const int row = p*16 + rsub;
        float4 acc = make_float4(0.f, 0.f, 0.f, 0.f);
        #pragma unroll 8
        for (int d = 0; d < DH; ++d) {
            const float qv = q_s[row*65 + d];
            const float4 kvv = *(const float4*)&kv_s[d*DH + e4];
            acc.x += qv*kvv.x; acc.y += qv*kvv.y; acc.z += qv*kvv.z; acc.w += qv*kvv.w;
        }
        const float inv = inv_s[row];
        float a4[4] = {acc.x*inv, acc.y*inv, acc.z*inv, acc.w*inv};
        unsigned hb[4], lb[4];
        #pragma unroll
        for (int i = 0; i < 4; i++) {
            const bf16 hv = __float2bfloat16(a4[i]);
            const float r = a4[i] - __bfloat162float(hv);
            hb[i] = (unsigned)__bfloat16_as_ushort(hv);
            lb[i] = (unsigned)__bfloat16_as_ushort(__float2bfloat16(r));
        }
        uint2 uh, ul;
        uh.x = hb[0] | (hb[1] << 16); uh.y = hb[2] | (hb[3] << 16);
        ul.x = lb[0] | (lb[1] << 16); ul.y = lb[2] | (lb[3] << 16);
        const size_t off = (size_t)(b*SEQ + base + row)*CH + h*DH + e4;
        *(uint2*)(g_attn_hi + off) = uh;
        *(uint2*)(g_attn_lo + off) = ul;
    }
}

// ------------------------- launch -------------------------
extern "C" void kernel_launch(void* const* d_in, const int* in_sizes, int n_in,
                              void* d_out, int out_size) {
    (void)in_sizes; (void)n_in; (void)out_size;
    const float* x     = (const float*)d_in[0];
    const float* w_qkv = (const float*)d_in[1];
    const float* w_out = (const float*)d_in[2];
    const float* b_out = (const float*)d_in[3];
    float* out = (float*)d_out;

    split_kernel<<<4096, 256>>>(x,     MROWS*KDIM, 0);
    split_kernel<<<2048, 256>>>(w_qkv, NQKV*KDIM,  1);
    split_kernel<<<1024, 256>>>(w_out, CH*KDIM,    2);

    cudaFuncSetAttribute(gemm_bf16x3<0>, cudaFuncAttributeMaxDynamicSharedMemorySize, (int)GEMM_SMEM);
    gemm_bf16x3<0><<<dim3(NQKV/BN, MROWS/BM), 256, GEMM_SMEM>>>(nullptr, nullptr);

    kv_partial_kernel<<<dim3(NSPLIT, BHCNT), 256>>>();
    kv_reduce_kernel<<<(BHCNT*DH*DH)/256, 256>>>();
    denom_kernel<<<dim3(SEQ/256, BHCNT), 256>>>();
    attn_kernel<<<dim3(SEQ/64, BHCNT), 256>>>();

    cudaFuncSetAttribute(gemm_bf16x3<1>, cudaFuncAttributeMaxDynamicSharedMemorySize, (int)GEMM_SMEM);
    gemm_bf16x3<1><<<dim3(CH/BN, MROWS/BM), 256, GEMM_SMEM>>>(out, b_out);
}

// round 7
// speedup vs baseline: 1.0512x; 1.0512x over previous
#include <cuda_runtime.h>
#include <cuda_bf16.h>
#include <mma.h>
#include <cstdint>

using namespace nvcuda;
typedef __nv_bfloat16 bf16;

#define BATCH 4
#define SEQ   4096
#define CH    1024
#define NHEAD 16
#define DH    64
#define MROWS (BATCH*SEQ)     /* 16384 */
#define KDIM  CH              /* 1024  */
#define NQKV  (3*CH)          /* 3072  */
#define NSPLIT 16
#define BHCNT (BATCH*NHEAD)   /* 64    */

// GEMM tiling
#define BM 128
#define BN 128
#define BK 32
#define NT (KDIM/BK)            /* 32 K-tiles */
#define STAGES 4
#define LDA 40                  /* bf16 elems; 80 B row stride (16B-aligned) */
#define ARR_BYTES (128*LDA*2)   /* 10240 B per array (Ah/Al/Bh/Bl)          */
#define STAGE_BYTES (4*ARR_BYTES)          /* 40960  */
#define GEMM_SMEM (STAGES*STAGE_BYTES)     /* 163840 */

// ------------------------- scratch (device globals; no allocs) -------------------------
__device__ bf16  g_x_hi[(size_t)MROWS*KDIM];
__device__ bf16  g_x_lo[(size_t)MROWS*KDIM];
__device__ bf16  g_wqkv_hi[(size_t)NQKV*KDIM];
__device__ bf16  g_wqkv_lo[(size_t)NQKV*KDIM];
__device__ bf16  g_wout_hi[(size_t)CH*KDIM];
__device__ bf16  g_wout_lo[(size_t)CH*KDIM];
__device__ float g_qkv[(size_t)MROWS*NQKV];
__device__ float g_kv_part[(size_t)NSPLIT*BHCNT*DH*DH];
__device__ float g_ksum_part[(size_t)NSPLIT*BHCNT*DH];
__device__ float g_kv[(size_t)BHCNT*DH*DH];
__device__ float g_denom[(size_t)BHCNT*SEQ];
__device__ bf16  g_attn_hi[(size_t)MROWS*CH];
__device__ bf16  g_attn_lo[(size_t)MROWS*CH];

// ------------------------- helpers -------------------------
__device__ __forceinline__ uint32_t smem_u32(const void* p) {
    uint32_t a;
    asm("{ .reg .u64 t; cvta.to.shared.u64 t, %1; cvt.u32.u64 %0, t; }" : "=r"(a) : "l"(p));
    return a;
}
__device__ __forceinline__ void cp_async16(uint32_t s, const void* g) {
    asm volatile("cp.async.cg.shared.global [%0], [%1], 16;" :: "r"(s), "l"(g) : "memory");
}
__device__ __forceinline__ void cp_commit() {
    asm volatile("cp.async.commit_group;" ::: "memory");
}
template<int N>
__device__ __forceinline__ void cp_wait() {
    asm volatile("cp.async.wait_group %0;" :: "n"(N) : "memory");
}
__device__ __forceinline__ float featf(float x) {
    const float s = 0.35355339059327373f;       // 64^-0.25
    return (x > 0.0f) ? (x + 1.0f) * s : __expf(x) * s;
}

// ------------------------- split fp32 -> bf16 hi/lo -------------------------
__global__ void split_kernel(const float* __restrict__ src, int n, int mode) {
    bf16 *hi, *lo;
    if (mode == 0)      { hi = g_x_hi;    lo = g_x_lo; }
    else if (mode == 1) { hi = g_wqkv_hi; lo = g_wqkv_lo; }
    else                { hi = g_wout_hi; lo = g_wout_lo; }
    int i = blockIdx.x * blockDim.x + threadIdx.x;
    int stride = gridDim.x * blockDim.x;
    for (; i < n; i += stride) {
        float v = src[i];
        bf16 h = __float2bfloat16(v);
        float r = v - __bfloat162float(h);
        hi[i] = h;
        lo[i] = __float2bfloat16(r);
    }
}

// ------------------------- bf16x3 GEMM with cp.async 4-stage pipeline -------------------------
// C[m,n] = sum_k A[m,k]*B[n,k]
// MODE 0: x @ wqkv^T, feat epilogue on q,k cols -> g_qkv.  MODE 1: attn @ wout^T + bias -> Cout.
template<int MODE>
__global__ void __launch_bounds__(256) gemm_bf16x3(float* __restrict__ CoutExt,
                                                   const float* __restrict__ bias) {
    constexpr int NC = (MODE == 0) ? NQKV : CH;
    const bf16* __restrict__ Ahi = (MODE == 0) ? g_x_hi    : g_attn_hi;
    const bf16* __restrict__ Alo = (MODE == 0) ? g_x_lo    : g_attn_lo;
    const bf16* __restrict__ Bhi = (MODE == 0) ? g_wqkv_hi : g_wout_hi;
    const bf16* __restrict__ Blo = (MODE == 0) ? g_wqkv_lo : g_wout_lo;
    float* __restrict__ Cp = (MODE == 0) ? g_qkv : CoutExt;

    extern __shared__ __align__(16) char smem_raw[];
    const uint32_t sb = smem_u32(smem_raw);

    const int tid = threadIdx.x;
    const int wid = tid >> 5;
    const int wm_ = wid >> 1;    // 0..3 (M dir, 32 rows each)
    const int wn_ = wid & 1;     // 0..1 (N dir, 64 cols each)
    const int m0 = blockIdx.y * BM;
    const int n0 = blockIdx.x * BN;

    // Per-thread cp.async slots: 2048 16B-chunks per stage, 8 per thread.
    // idx = tid + j*256: arr = idx>>9 (0:Ah 1:Al 2:Bh 3:Bl), r=(idx>>2)&127, c16=idx&3
    const char* gptr[8];
    uint32_t    sptr[8];
    #pragma unroll
    for (int j = 0; j < 8; ++j) {
        const int idx = tid + j * 256;
        const int arr = idx >> 9, r = (idx >> 2) & 127, c16 = idx & 3;
        const bf16* base = (arr == 0) ? Ahi : (arr == 1) ? Alo : (arr == 2) ? Bhi : Blo;
        const int row = ((arr < 2) ? m0 : n0) + r;
        gptr[j] = (const char*)(base + (size_t)row * KDIM + c16 * 8);
        sptr[j] = sb + arr * ARR_BYTES + r * (LDA * 2) + c16 * 16;
    }

    wmma::fragment<wmma::accumulator,16,16,16,float> acc[2][4];
    #pragma unroll
    for (int i = 0; i < 2; i++)
        #pragma unroll
        for (int j = 0; j < 4; j++) wmma::fill_fragment(acc[i][j], 0.0f);

    // prologue: stages 0..STAGES-2
    #pragma unroll
    for (int s = 0; s < STAGES - 1; ++s) {
        const uint32_t so = (uint32_t)(s & (STAGES-1)) * STAGE_BYTES;
        #pragma unroll
        for (int j = 0; j < 8; ++j) cp_async16(sptr[j] + so, gptr[j] + (size_t)s * (BK*2));
        cp_commit();
    }

    for (int kt = 0; kt < NT; ++kt) {
        cp_wait<STAGES - 2>();
        __syncthreads();

        // issue next stage (always commit, keeps wait_group accounting uniform)
        const int ns = kt + STAGES - 1;
        if (ns < NT) {
            const uint32_t so = (uint32_t)(ns & (STAGES-1)) * STAGE_BYTES;
            #pragma unroll
            for (int j = 0; j < 8; ++j) cp_async16(sptr[j] + so, gptr[j] + (size_t)ns * (BK*2));
        }
        cp_commit();

        const bf16* sA_h = (const bf16*)(smem_raw + (size_t)(kt & (STAGES-1)) * STAGE_BYTES);
        const bf16* sA_l = sA_h + 128*LDA;
        const bf16* sB_h = sA_l + 128*LDA;
        const bf16* sB_l = sB_h + 128*LDA;
        const bf16* pAh = sA_h + wm_*32*LDA;
        const bf16* pAl = sA_l + wm_*32*LDA;
        const bf16* pBh = sB_h + wn_*64*LDA;
        const bf16* pBl = sB_l + wn_*64*LDA;

        #pragma unroll
        for (int ks = 0; ks < BK; ks += 16) {
            wmma::fragment<wmma::matrix_a,16,16,16,bf16,wmma::row_major> ah[2], al[2];
            #pragma unroll
            for (int i = 0; i < 2; i++) {
                wmma::load_matrix_sync(ah[i], pAh + i*16*LDA + ks, LDA);
                wmma::load_matrix_sync(al[i], pAl + i*16*LDA + ks, LDA);
            }
            #pragma unroll
            for (int j = 0; j < 4; j++) {
                wmma::fragment<wmma::matrix_b,16,16,16,bf16,wmma::col_major> bh, bl;
                wmma::load_matrix_sync(bh, pBh + j*16*LDA + ks, LDA);
                wmma::load_matrix_sync(bl, pBl + j*16*LDA + ks, LDA);
                wmma::mma_sync(acc[0][j], ah[0], bh, acc[0][j]);
                wmma::mma_sync(acc[1][j], ah[1], bh, acc[1][j]);
                wmma::mma_sync(acc[0][j], ah[0], bl, acc[0][j]);
                wmma::mma_sync(acc[1][j], ah[1], bl, acc[1][j]);
                wmma::mma_sync(acc[0][j], al[0], bh, acc[0][j]);
                wmma::mma_sync(acc[1][j], al[1], bh, acc[1][j]);
            }
        }
        __syncthreads();
    }
    cp_wait<0>();
    __syncthreads();

    // epilogue: stage accumulators in smem, then vectorized global store with fusion
    float* Cs = (float*)smem_raw;   // 128 x 132 floats = 67584 B (fits in 163840)
    #pragma unroll
    for (int i = 0; i < 2; i++)
        #pragma unroll
        for (int j = 0; j < 4; j++)
            wmma::store_matrix_sync(Cs + (wm_*32 + i*16)*132 + wn_*64 + j*16,
                                    acc[i][j], 132, wmma::mem_row_major);
    __syncthreads();
    for (int i = tid; i < BM*BN/4; i += 256) {
        const int row = i >> 5;
        const int c4  = (i & 31) << 2;
        float4 v = *(const float4*)&Cs[row*132 + c4];
        const int gn = n0 + c4;
        if (MODE == 0) {
            if (gn < 2*CH) {  // q and k columns get elu+1 and scale
                v.x = featf(v.x); v.y = featf(v.y); v.z = featf(v.z); v.w = featf(v.w);
            }
        } else {
            v.x += bias[gn]; v.y += bias[gn+1]; v.z += bias[gn+2]; v.w += bias[gn+3];
        }
        *(float4*)&Cp[(size_t)(m0 + row)*NC + gn] = v;
    }
}

// ------------------------- kv = k^T v partials + ksum partials -------------------------
__global__ void __launch_bounds__(256) kv_partial_kernel() {
    const int s  = blockIdx.x;
    const int bh = blockIdx.y;
    const int b = bh >> 4, h = bh & 15;
    const int tid = threadIdx.x;
    const int d  = tid >> 2;
    const int e0 = (tid & 3) << 4;

    __shared__ __align__(16) float ks_[8][64];
    __shared__ __align__(16) float vs_[8][64];

    float acc[16];
    #pragma unroll
    for (int i = 0; i < 16; i++) acc[i] = 0.0f;
    float ksum = 0.0f;

    const float* kbase = g_qkv + (size_t)(b*SEQ)*NQKV + CH + h*DH;
    const float* vbase = kbase + CH;
    int nbase = s * (SEQ / NSPLIT);
    for (int it = 0; it < 32; ++it, nbase += 8) {
        #pragma unroll
        for (int j = 0; j < 2; ++j) {
            const int idx = tid + j*256;
            const int r = idx >> 6, c = idx & 63;
            ks_[r][c] = kbase[(size_t)(nbase + r)*NQKV + c];
            vs_[r][c] = vbase[(size_t)(nbase + r)*NQKV + c];
        }
        __syncthreads();
        #pragma unroll
        for (int r = 0; r < 8; ++r) {
            const float kd = ks_[r][d];
            ksum += kd;
            #pragma unroll
            for (int j4 = 0; j4 < 4; ++j4) {
                const float4 vv = *(const float4*)&vs_[r][e0 + j4*4];
                acc[j4*4+0] += kd*vv.x; acc[j4*4+1] += kd*vv.y;
                acc[j4*4+2] += kd*vv.z; acc[j4*4+3] += kd*vv.w;
            }
        }
        __syncthreads();
    }
    float* outp = g_kv_part + ((size_t)s*BHCNT + bh)*(DH*DH) + d*DH + e0;
    #pragma unroll
    for (int j4 = 0; j4 < 4; ++j4)
        *(float4*)&outp[j4*4] = make_float4(acc[j4*4], acc[j4*4+1], acc[j4*4+2], acc[j4*4+3]);
    if ((tid & 3) == 0)
        g_ksum_part[((size_t)s*BHCNT + bh)*DH + d] = ksum;
}

__global__ void kv_reduce_kernel() {
    const int i = blockIdx.x * 256 + threadIdx.x;
    float s = 0.0f;
    #pragma unroll
    for (int p = 0; p < NSPLIT; ++p) s += g_kv_part[(size_t)p*(BHCNT*DH*DH) + i];
    g_kv[i] = s;
}

// ------------------------- ksum reduce + denom^-1 -------------------------
__global__ void __launch_bounds__(256) denom_kernel() {
    const int bh = blockIdx.y;
    const int b = bh >> 4, h = bh & 15;
    const int tid = threadIdx.x;
    __shared__ float ksum_s[64];
    if (tid < 64) {
        float s = 0.0f;
        #pragma unroll
        for (int p = 0; p < NSPLIT; ++p) s += g_ksum_part[((size_t)p*BHCNT + bh)*DH + tid];
        ksum_s[tid] = s;
    }
    __syncthreads();
    const int n = blockIdx.x * 256 + tid;
    const float* qp = g_qkv + (size_t)(b*SEQ + n)*NQKV + h*DH;
    float a = 0.0f;
    #pragma unroll
    for (int d4 = 0; d4 < DH; d4 += 4) {
        const float4 q4 = *(const float4*)&qp[d4];
        a += q4.x*ksum_s[d4] + q4.y*ksum_s[d4+1] + q4.z*ksum_s[d4+2] + q4.w*ksum_s[d4+3];
    }
    g_denom[(size_t)bh*SEQ + n] = 1.0f / (a + 1e-6f);
}

// ------------------------- out = (q @ kv) * denom^-1, split to bf16 hi/lo -------------------------
__global__ void __launch_bounds__(256) attn_kernel() {
    const int bh = blockIdx.y;
    const int chunk = blockIdx.x;
    const int b = bh >> 4, h = bh & 15;
    const int tid = threadIdx.x;
    const int base = chunk * 64;

    __shared__ __align__(16) float kv_s[64*64];
    __shared__ float q_s[64*65];
    __shared__ float inv_s[64];

    for (int i = tid; i < DH*DH; i += 256) kv_s[i] = g_kv[(size_t)bh*(DH*DH) + i];
    for (int i = tid; i < 64*64; i += 256) {
        const int r = i >> 6, d = i & 63;
        q_s[r*65 + d] = g_qkv[(size_t)(b*SEQ + base + r)*NQKV + h*DH + d];
    }
    if (tid < 64) inv_s[tid] = g_denom[(size_t)bh*SEQ + base + tid];
    __syncthreads();

    const int rsub = tid >> 4;
    const int e4   = (tid & 15) << 2;
    #pragma unroll
    for (int p = 0; p < 4; ++p) {
        const int row = p*16 + rsub;
        float4 acc = make_float4(0.f, 0.f, 0.f, 0.f);
        #pragma unroll 8
        for (int d = 0; d < DH; ++d) {
            const float qv = q_s[row*65 + d];
            const float4 kvv = *(const float4*)&kv_s[d*DH + e4];
            acc.x += qv*kvv.x; acc.y += qv*kvv.y; acc.z += qv*kvv.z; acc.w += qv*kvv.w;
        }
        const float inv = inv_s[row];
        float a4[4] = {acc.x*inv, acc.y*inv, acc.z*inv, acc.w*inv};
        unsigned hb[4], lb[4];
        #pragma unroll
        for (int i = 0; i < 4; i++) {
            const bf16 hv = __float2bfloat16(a4[i]);
            const float r = a4[i] - __bfloat162float(hv);
            hb[i] = (unsigned)__bfloat16_as_ushort(hv);
            lb[i] = (unsigned)__bfloat16_as_ushort(__float2bfloat16(r));
        }
        uint2 uh, ul;
        uh.x = hb[0] | (hb[1] << 16); uh.y = hb[2] | (hb[3] << 16);
        ul.x = lb[0] | (lb[1] << 16); ul.y = lb[2] | (lb[3] << 16);
        const size_t off = (size_t)(b*SEQ + base + row)*CH + h*DH + e4;
        *(uint2*)(g_attn_hi + off) = uh;
        *(uint2*)(g_attn_lo + off) = ul;
    }
}

// ------------------------- launch -------------------------
extern "C" void kernel_launch(void* const* d_in, const int* in_sizes, int n_in,
                              void* d_out, int out_size) {
    (void)in_sizes; (void)n_in; (void)out_size;
    const float* x     = (const float*)d_in[0];
    const float* w_qkv = (const float*)d_in[1];
    const float* w_out = (const float*)d_in[2];
    const float* b_out = (const float*)d_in[3];
    float* out = (float*)d_out;

    split_kernel<<<4096, 256>>>(x,     MROWS*KDIM, 0);
    split_kernel<<<2048, 256>>>(w_qkv, NQKV*KDIM,  1);
    split_kernel<<<1024, 256>>>(w_out, CH*KDIM,    2);

    cudaFuncSetAttribute(gemm_bf16x3<0>, cudaFuncAttributeMaxDynamicSharedMemorySize, (int)GEMM_SMEM);
    gemm_bf16x3<0><<<dim3(NQKV/BN, MROWS/BM), 256, GEMM_SMEM>>>(nullptr, nullptr);

    kv_partial_kernel<<<dim3(NSPLIT, BHCNT), 256>>>();
    kv_reduce_kernel<<<(BHCNT*DH*DH)/256, 256>>>();
    denom_kernel<<<dim3(SEQ/256, BHCNT), 256>>>();
    attn_kernel<<<dim3(SEQ/64, BHCNT), 256>>>();

    cudaFuncSetAttribute(gemm_bf16x3<1>, cudaFuncAttributeMaxDynamicSharedMemorySize, (int)GEMM_SMEM);
    gemm_bf16x3<1><<<dim3(CH/BN, MROWS/BM), 256, GEMM_SMEM>>>(out, b_out);
}